// round 8
// baseline (speedup 1.0000x reference)
#include <cuda_runtime.h>
#include <cstdint>

#define NB 8
#define S_LEN 4096
#define D 1024
#define D4 (D / 4)                       // 256 float4 per row
#define CHUNKS 64
#define ROWS_PER_CHUNK (S_LEN / CHUNKS)  // 64

// Scratch (allocation-free rule: __device__ globals)
__device__ float g_partial[NB * CHUNKS * D];  // 2 MB
__device__ float g_vsum[NB * D];
__device__ float g_tmp[NB * D];

// ---------------------------------------------------------------------------
// Stage 1: partial column-sum of V over a 64-row chunk.
// grid = (CHUNKS, NB) = 512 blocks, block = 256. Thread t owns float4 col t.
__global__ void __launch_bounds__(256) reduce_partial(const float4* __restrict__ V) {
    const int t = threadIdx.x;
    const int c = blockIdx.x;
    const int n = blockIdx.y;
    const float4* base =
        V + ((size_t)n * S_LEN + (size_t)c * ROWS_PER_CHUNK) * D4 + t;
    float4 a0 = make_float4(0.f, 0.f, 0.f, 0.f);
    float4 a1 = a0, a2 = a0, a3 = a0;
#pragma unroll 4
    for (int s = 0; s < ROWS_PER_CHUNK; s += 4) {
        float4 v0 = base[(size_t)(s + 0) * D4];
        float4 v1 = base[(size_t)(s + 1) * D4];
        float4 v2 = base[(size_t)(s + 2) * D4];
        float4 v3 = base[(size_t)(s + 3) * D4];
        a0.x += v0.x; a0.y += v0.y; a0.z += v0.z; a0.w += v0.w;
        a1.x += v1.x; a1.y += v1.y; a1.z += v1.z; a1.w += v1.w;
        a2.x += v2.x; a2.y += v2.y; a2.z += v2.z; a2.w += v2.w;
        a3.x += v3.x; a3.y += v3.y; a3.z += v3.z; a3.w += v3.w;
    }
    float4 acc;
    acc.x = (a0.x + a1.x) + (a2.x + a3.x);
    acc.y = (a0.y + a1.y) + (a2.y + a3.y);
    acc.z = (a0.z + a1.z) + (a2.z + a3.z);
    acc.w = (a0.w + a1.w) + (a2.w + a3.w);
    reinterpret_cast<float4*>(g_partial)[((size_t)n * CHUNKS + c) * D4 + t] = acc;
}

// ---------------------------------------------------------------------------
// Stage 2: fold the 64 partials, parallel over columns.
// grid = NB * 8 = 64 blocks, block = 256 (8 k-slices x 32 cols).
__global__ void __launch_bounds__(256) reduce_final() {
    __shared__ float4 sred[8][32];
    const int t = threadIdx.x;
    const int lane = t & 31;
    const int slice = t >> 5;
    const int n  = blockIdx.x >> 3;
    const int cg = blockIdx.x & 7;
    const int col = cg * 32 + lane;

    const float4* p =
        reinterpret_cast<const float4*>(g_partial) + (size_t)n * CHUNKS * D4 + col;
    float4 a = make_float4(0.f, 0.f, 0.f, 0.f);
#pragma unroll
    for (int c = 0; c < 8; ++c) {
        float4 v = p[(size_t)(slice * 8 + c) * D4];
        a.x += v.x; a.y += v.y; a.z += v.z; a.w += v.w;
    }
    sred[slice][lane] = a;
    __syncthreads();
    if (slice == 0) {
        float4 s = sred[0][lane];
#pragma unroll
        for (int k = 1; k < 8; ++k) {
            float4 v = sred[k][lane];
            s.x += v.x; s.y += v.y; s.z += v.z; s.w += v.w;
        }
        reinterpret_cast<float4*>(g_vsum)[n * D4 + col] = s;
    }
}

// ---------------------------------------------------------------------------
// Batch-8 GEMV via cp.async-staged tiles.
// grid = 128 blocks (8 j each), block = 256.
// Warp (jg, ks): jg = wid>>2 owns j-quad, ks = wid&3 owns a k quarter.
// LDGSTS has no dest register -> all 16 copies issue back-to-back (true MLP).
#define JPB 8
#define GEMV_SMEM (4096 * 16 + 256 * 4)  // xs(32K) + ws(32K) + sout(1K)

__device__ __forceinline__ void cpa16(uint32_t dst_smem, const void* src) {
    asm volatile("cp.async.cg.shared.global [%0], [%1], 16;"
                 :: "r"(dst_smem), "l"(src));
}

__global__ void __launch_bounds__(256) gemv8(const float4* __restrict__ W,
                                             const float* __restrict__ b,
                                             float bias_scale, int stage,
                                             float* __restrict__ dout) {
    extern __shared__ float4 dyn[];
    float4* xs   = dyn;                       // 2048 float4 (x: 8 x 256)
    float4* ws   = dyn + 2048;                // 2048 float4 (W tile: 8 rows)
    float*  sout = reinterpret_cast<float*>(dyn + 4096);  // [4 ks][8 j][8 n]

    const int t = threadIdx.x;
    const int lane = t & 31;
    const int wid = t >> 5;

    const float4* xin = reinterpret_cast<const float4*>(stage == 0 ? g_vsum : g_tmp);
    float* out = (stage == 0) ? g_tmp : dout;

    // Async-stage both tiles: 16 LDGSTS/thread, zero register pressure.
    const uint32_t xs_a = (uint32_t)__cvta_generic_to_shared(xs);
    const uint32_t ws_a = (uint32_t)__cvta_generic_to_shared(ws);
    const float4* Wp = W + (size_t)blockIdx.x * JPB * D4;
#pragma unroll
    for (int i = 0; i < 8; ++i)
        cpa16(xs_a + (t + i * 256) * 16, xin + t + i * 256);
#pragma unroll
    for (int i = 0; i < 8; ++i)
        cpa16(ws_a + (t + i * 256) * 16, Wp + t + i * 256);
    asm volatile("cp.async.commit_group;");
    asm volatile("cp.async.wait_group 0;");
    __syncthreads();

    const int jg = wid >> 2;   // 0..1: j-quad
    const int ks = wid & 3;    // 0..3: k quarter (2 chunks of 32 float4)

    float acc[4][NB];
#pragma unroll
    for (int j = 0; j < 4; ++j)
#pragma unroll
        for (int n = 0; n < NB; ++n) acc[j][n] = 0.f;

#pragma unroll
    for (int ii = 0; ii < 2; ++ii) {
        const int c = ks * 2 + ii;           // k chunk 0..7
        float4 w4[4];
#pragma unroll
        for (int j = 0; j < 4; ++j)
            w4[j] = ws[(jg * 4 + j) * D4 + c * 32 + lane];
#pragma unroll
        for (int n = 0; n < NB; ++n) {
            float4 x = xs[n * D4 + c * 32 + lane];
#pragma unroll
            for (int j = 0; j < 4; ++j) {
                acc[j][n] += w4[j].x * x.x + w4[j].y * x.y +
                             w4[j].z * x.z + w4[j].w * x.w;
            }
        }
    }

    // 32 independent warp reductions.
#pragma unroll
    for (int j = 0; j < 4; ++j)
#pragma unroll
        for (int n = 0; n < NB; ++n) {
#pragma unroll
            for (int ofs = 16; ofs > 0; ofs >>= 1)
                acc[j][n] += __shfl_xor_sync(0xFFFFFFFFu, acc[j][n], ofs);
        }

    if (lane == 0) {
#pragma unroll
        for (int j = 0; j < 4; ++j)
#pragma unroll
            for (int n = 0; n < NB; ++n)
                sout[ks * 64 + (jg * 4 + j) * NB + n] = acc[j][n];
    }
    __syncthreads();

    // Fold the 4 k-quarters; 64 outputs per block.
    if (t < JPB * NB) {
        const int jl = t >> 3;
        const int n  = t & 7;
        const int j  = blockIdx.x * JPB + jl;
        float s = sout[jl * NB + n] + sout[64 + jl * NB + n] +
                  sout[128 + jl * NB + n] + sout[192 + jl * NB + n];
        out[n * D + j] = s + bias_scale * b[j];
    }
}

// ---------------------------------------------------------------------------
extern "C" void kernel_launch(void* const* d_in, const int* in_sizes, int n_in,
                              void* d_out, int out_size) {
    (void)in_sizes; (void)n_in; (void)out_size;
    // metadata order: Q(0) K(1) V(2) Wq(3) bq(4) Wk(5) bk(6) Wv(7) bv(8) Wo(9) bo(10)
    // softmax over a size-1 axis == 1.0 -> Q, K, Wq, bq, Wk, bk are dead inputs.
    const float4* V  = (const float4*)d_in[2];
    const float4* Wv = (const float4*)d_in[7];
    const float*  bv = (const float*)d_in[8];
    const float4* Wo = (const float4*)d_in[9];
    const float*  bo = (const float*)d_in[10];
    float* out = (float*)d_out;

    // Not a stream op; safe under graph capture. Idempotent.
    cudaFuncSetAttribute(gemv8, cudaFuncAttributeMaxDynamicSharedMemorySize,
                         GEMV_SMEM);

    reduce_partial<<<dim3(CHUNKS, NB), 256>>>(V);
    reduce_final<<<NB * 8, 256>>>();
    gemv8<<<D / JPB, 256, GEMV_SMEM>>>(Wv, bv, (float)S_LEN, 0, nullptr);
    gemv8<<<D / JPB, 256, GEMV_SMEM>>>(Wo, bo, 1.0f, 1, out);
}